// round 17
// baseline (speedup 1.0000x reference)
#include <cuda_runtime.h>

#define HH 384
#define WW 384
#define BB 8
#define CC 4
#define NPIX (HH*WW)        // 147456
#define BIGF 1e8f
#define DINF (1 << 28)

#define ST 8                // k_loss h-strip per block
#define NST (HH / ST)       // 48
#define NBLK (BB * NST)     // 384 k_loss blocks

// Signed row-pass field, AoS per pixel: g_w[((b*HH+h)*WW+x)*4 + c]
//   = (t==c) ? -dne^2 (or -BIG) : +deq^2 (or +BIG)
__device__ float g_w[(unsigned)BB * NPIX * CC];   // ~18.9 MB
__device__ float g_part[NBLK];
__device__ int   g_ctr = 0;                       // reset by last block each launch

// ---------------------------------------------------------------------------
// Rare-path exact full-row scan (12 words) for nearest set bit.
__device__ int full_scan(const unsigned* __restrict__ words, int x) {
    int w0 = x >> 5, b0 = x & 31;
    unsigned wv = words[w0];

    int dl = DINF;
    unsigned curl = wv & (0xFFFFFFFFu >> (31 - b0));
    int wl = w0;
    while (curl == 0 && wl > 0) { --wl; curl = words[wl]; }
    if (curl) dl = x - (wl * 32 + (31 - __clz(curl)));

    int dr = DINF;
    unsigned curr = wv & (0xFFFFFFFFu << b0);
    int wr = w0;
    while (curr == 0 && wr < 11) { ++wr; curr = words[wr]; }
    if (curr) dr = (wr * 32 + (__ffs(curr) - 1)) - x;

    return min(dl, dr);
}

// Min |i-16| over set bits of a 32-bit window (bit 16 = self); DINF if 0.
__device__ __forceinline__ int wdist32(unsigned win) {
    unsigned low  = win & 0x1FFFFu;   // bits 0..16
    unsigned high = win >> 16;        // bits 16..31
    int dl = low  ? (__clz(low) - 15) : DINF;
    int dr = high ? (__ffs(high) - 1) : DINF;
    return min(dl, dr);
}

// ---------------------------------------------------------------------------
// Row pass: one block per (b,h) row; 384 threads. Per class, 32-bit
// funnel-shift window [x-16, x+15] with exact full-scan fallback.
// Own-class complement distance derived exactly: dne(t) = min_{c!=t} deq(c)
// (nearest different-class pixel = min over other classes' nearests).
// One float4 store per pixel.
__global__ void k_rowpass(const int* __restrict__ targets) {
    __shared__ unsigned Wp[CC][14];   // padded: [0] and [13] zero

    int b = blockIdx.x / HH;
    int h = blockIdx.x % HH;
    int x = threadIdx.x;
    int warp = x >> 5, lane = x & 31;

    int t = targets[(b * HH + h) * WW + x];

#pragma unroll
    for (int c = 0; c < CC; ++c) {
        unsigned m = __ballot_sync(0xFFFFFFFFu, t == c);
        if (lane == 0) Wp[c][warp + 1] = m;
    }
    if (x < CC) { Wp[x][0] = 0; Wp[x][13] = 0; }
    __syncthreads();

    int start = x - 16;
    int j2 = (start >> 5) + 1;        // padded word index
    int sh = start & 31;

    int de[CC];
#pragma unroll
    for (int c = 0; c < CC; ++c) {
        unsigned win = __funnelshift_r(Wp[c][j2], Wp[c][j2 + 1], sh);
        de[c] = win ? wdist32(win) : full_scan(&Wp[c][1], x);
    }

    int dn = DINF;
#pragma unroll
    for (int c = 0; c < CC; ++c)
        if (c != t) dn = min(dn, de[c]);

    float w_own = (dn >= DINF) ? -BIGF : -((float)dn * (float)dn);

    float wout[CC];
#pragma unroll
    for (int c = 0; c < CC; ++c) {
        float v = (de[c] >= DINF) ? BIGF : ((float)de[c] * (float)de[c]);
        wout[c] = (c == t) ? w_own : v;
    }

    float4 o = make_float4(wout[0], wout[1], wout[2], wout[3]);
    *reinterpret_cast<float4*>(g_w + ((unsigned)(b * HH + h) * WW + x) * 4) = o;
}

// ---------------------------------------------------------------------------
// Rare exact vertical tail from dh=5 (only when window best > 25).
__device__ __noinline__ float tail_min(const float* __restrict__ pc,
                                       float best, float sgn, int h) {
    float q = 25.0f, stp = 11.0f;
    int hm = h - 5, hp = h + 5;
#pragma unroll 1
    for (int dh = 5; dh < HH; ++dh) {
        if (q >= best) break;
        if (hm >= 0) {
            float v = __ldg(pc + hm * (WW * 4));
            best = fminf(best, fmaxf(fmaf(sgn, v, q), q));
        }
        if (hp < HH) {
            float v = __ldg(pc + hp * (WW * 4));
            best = fminf(best, fmaxf(fmaf(sgn, v, q), q));
        }
        q += stp; stp += 2.0f; --hm; ++hp;
    }
    return best;
}

// ---------------------------------------------------------------------------
// Rolling-window strip: thread owns column w of an 8-row strip; 9 float4 rows
// live in registers, shifted down the strip (1 new load per pixel). Single-
// polarity ring (membership from sign of center): candidate = max(sgn*v+q, q).
// Extra dh<=4 iterations past the true radius are exact no-ops.
template <bool EDGE>
__device__ __forceinline__ float strip_loss(const float* __restrict__ logits,
                                            int b, int h0, int w) {
    const float4* gw4 = reinterpret_cast<const float4*>(g_w);

    float4 win[9];
#pragma unroll
    for (int i = 0; i < 9; ++i) {
        int r = h0 - 4 + i;
        int rr = EDGE ? min(max(r, 0), HH - 1) : r;
        win[i] = __ldg(gw4 + ((unsigned)(b * HH + rr) * WW + w));
    }

    float acc = 0.0f;
#pragma unroll
    for (int j = 0; j < ST; ++j) {
        int h = h0 + j;

        // softmax
        int rbase = (b * CC) * NPIX + h * WW + w;
        float l0 = logits[rbase];
        float l1 = logits[rbase + NPIX];
        float l2 = logits[rbase + 2 * NPIX];
        float l3 = logits[rbase + 3 * NPIX];
        float mx = fmaxf(fmaxf(l0, l1), fmaxf(l2, l3));
        float e0 = __expf(l0 - mx), e1 = __expf(l1 - mx);
        float e2 = __expf(l2 - mx), e3 = __expf(l3 - mx);
        float inv = 1.0f / (e0 + e1 + e2 + e3);
        float pr[4] = { e0 * inv, e1 * inv, e2 * inv, e3 * inv };

#pragma unroll
        for (int c = 0; c < CC; ++c) {
            float v0 = reinterpret_cast<const float*>(&win[4])[c];
            float sgn = (v0 < 0.0f) ? -1.0f : 1.0f;
            float best = sgn * v0;             // = |v0|
#pragma unroll
            for (int i = 0; i < 9; ++i) {
                if (i == 4) continue;
                float q = (float)((i - 4) * (i - 4));
                float v = reinterpret_cast<const float*>(&win[i])[c];
                float cand = fmaxf(fmaf(sgn, v, q), q);
                if (EDGE) {
                    int r = h - 4 + i;
                    if (r < 0 || r >= HH) cand = BIGF;
                }
                best = fminf(best, cand);
            }

            if (best > 25.0f)
                best = tail_min(g_w + ((unsigned)(b * HH) * WW + w) * 4 + c,
                                best, sgn, h);

            // phi = sgn*sqrt(best) (+1 unless degenerate mask: best >= 1e7;
            // finite dist^2 <= 2*383^2 ~ 2.9e5 << 1e7)
            float phi = sgn * sqrtf(best);
            if (best < 1e7f) phi += 1.0f;
            acc += pr[c] * phi;
        }

        if (j < ST - 1) {
#pragma unroll
            for (int i = 0; i < 8; ++i) win[i] = win[i + 1];
            int r = h + 5;
            int rr = EDGE ? min(r, HH - 1) : r;
            win[8] = __ldg(gw4 + ((unsigned)(b * HH + rr) * WW + w));
        }
    }
    return acc;
}

__global__ void __launch_bounds__(384) k_loss(const float* __restrict__ logits,
                                              float* __restrict__ out) {
    int blk = blockIdx.x;
    int b = blk / NST;
    int s = blk - b * NST;
    int h0 = s * ST;
    int w = threadIdx.x;

    float acc = (s == 0 || s == NST - 1)
                    ? strip_loss<true>(logits, b, h0, w)
                    : strip_loss<false>(logits, b, h0, w);

    // block reduction (12 warps, fixed shape -> deterministic)
    int lane = threadIdx.x & 31, wid = threadIdx.x >> 5;
#pragma unroll
    for (int o = 16; o; o >>= 1) acc += __shfl_down_sync(0xFFFFFFFFu, acc, o);
    __shared__ float sm[12];
    __shared__ int s_last;
    if (lane == 0) sm[wid] = acc;
    __syncthreads();
    if (threadIdx.x < 32) {
        float v = (threadIdx.x < 12) ? sm[threadIdx.x] : 0.0f;
#pragma unroll
        for (int o = 8; o; o >>= 1) v += __shfl_down_sync(0xFFFFFFFFu, v, o);
        if (threadIdx.x == 0) {
            g_part[blk] = v;
            __threadfence();
            int n = atomicAdd(&g_ctr, 1);
            s_last = (n == NBLK - 1);
        }
    }
    __syncthreads();

    // Last block: final reduce of all 384 partials in FIXED order
    // (exactly one block, deterministic order -> replay-deterministic).
    if (s_last) {
        __threadfence();
        float v = __ldcg(&g_part[threadIdx.x]);
#pragma unroll
        for (int o = 16; o; o >>= 1) v += __shfl_down_sync(0xFFFFFFFFu, v, o);
        if (lane == 0) sm[wid] = v;
        __syncthreads();
        if (threadIdx.x < 32) {
            float u = (threadIdx.x < 12) ? sm[threadIdx.x] : 0.0f;
#pragma unroll
            for (int o = 8; o; o >>= 1) u += __shfl_down_sync(0xFFFFFFFFu, u, o);
            if (threadIdx.x == 0) {
                out[0] = u * (1.0f / ((float)BB * CC * NPIX));
                g_ctr = 0;    // reset for next graph replay
            }
        }
    }
}

// ---------------------------------------------------------------------------
extern "C" void kernel_launch(void* const* d_in, const int* in_sizes, int n_in,
                              void* d_out, int out_size) {
    const float* logits  = (const float*)d_in[0];
    const int*   targets = (const int*)d_in[1];
    float* out = (float*)d_out;

    k_rowpass<<<BB * HH, 384>>>(targets);
    k_loss<<<NBLK, 384>>>(logits, out);
}